// round 3
// baseline (speedup 1.0000x reference)
#include <cuda_runtime.h>
#include <math.h>

// Blobber fused single pass (the reference's 4 iterations are identical).
// out = sigma((box3(sigma((box3(in)-0.01)*1000)) - 0.9)*1000)
// Separable 3x1/1x3 box sums, 2D thread mapping, exp2-based 4-instr sigmoid.

#define IMG  512
#define TS   32          // output tile (32x32)
#define BYD  8           // blockDim.y

// sigma((s/9 - b)*1000) = 1 / (1 + exp2( b*1000*log2e - s*(1000/9)*log2e ))
#define LOG2E 1.4426950408889634f
#define SCL   (1000.0f / 9.0f * LOG2E)     // s coefficient in exponent
#define C1    (10.0f * LOG2E)              // b=0.01 -> 0.01*1000*log2e
#define C2    (900.0f * LOG2E)             // b=0.9  -> 0.9*1000*log2e

__device__ __forceinline__ float sig1(float s) {
    float e = exp2f(fmaf(s, -SCL, C1));
    return __fdividef(1.0f, 1.0f + e);
}
__device__ __forceinline__ float sig2(float s) {
    float e = exp2f(fmaf(s, -SCL, C2));
    return __fdividef(1.0f, 1.0f + e);
}

__global__ __launch_bounds__(TS * BYD)
void blobber_fused_kernel(const float* __restrict__ in, float* __restrict__ out) {
    // halo geometry: input region rows/cols [-2..33] (36), mid region [-1..32] (34)
    __shared__ float s_in [36][37];  // input halo
    __shared__ float s_h1 [36][35];  // horiz 3-sum of input: h1[r][c] = in[r][c..c+2], c in [0,34)
    __shared__ float s_mid[34][35];  // sigma(first conv), zeroed outside image
    __shared__ float s_h2 [34][33];  // horiz 3-sum of mid:   h2[r][c] = mid[r][c..c+2], c in [0,32)

    const int tx = threadIdx.x;          // 0..31
    const int ty = threadIdx.y;          // 0..7
    const int bx = blockIdx.x * TS;
    const int by = blockIdx.y * TS;

    const float* img  = in  + (size_t)blockIdx.z * IMG * IMG;
    float*       oimg = out + (size_t)blockIdx.z * IMG * IMG;

    // column validity (precomputed once per thread)
    const int  gc0   = bx + tx - 2;          // for s_in col tx
    const int  gc1   = bx + tx + 30;         // for s_in col tx+32 (tx<4)
    const bool cok0  = (unsigned)gc0 < (unsigned)IMG;
    const bool cok1  = (unsigned)gc1 < (unsigned)IMG;
    const bool mok0  = (unsigned)(bx + tx - 1) < (unsigned)IMG;   // mid col tx
    const bool mok1  = (unsigned)(bx + tx + 31) < (unsigned)IMG;  // mid col tx+32 (tx<2)

    // ---- load 36x36 input halo ----
    #pragma unroll
    for (int r = ty; r < 36; r += BYD) {
        const int gr = by + r - 2;
        const bool rok = (unsigned)gr < (unsigned)IMG;
        const float* row = img + (size_t)gr * IMG;
        s_in[r][tx] = (rok && cok0) ? row[gc0] : 0.0f;
        if (tx < 4)
            s_in[r][tx + 32] = (rok && cok1) ? row[gc1] : 0.0f;
    }
    __syncthreads();

    // ---- horizontal 3-sum of input: 36 rows x 34 cols ----
    #pragma unroll
    for (int r = ty; r < 36; r += BYD) {
        s_h1[r][tx] = s_in[r][tx] + s_in[r][tx + 1] + s_in[r][tx + 2];
        if (tx < 2)
            s_h1[r][tx + 32] = s_in[r][tx + 32] + s_in[r][tx + 33] + s_in[r][tx + 34];
    }
    __syncthreads();

    // ---- first conv (vertical 3-sum) + sigmoid -> mid: 34 rows x 34 cols ----
    // mid[r][c] is image pixel (by+r-1, bx+c-1); MUST be exactly 0 outside the
    // image (second conv zero-pads the sigmoid map).
    #pragma unroll
    for (int r = ty; r < 34; r += BYD) {
        const bool rok = (unsigned)(by + r - 1) < (unsigned)IMG;
        {
            float s = s_h1[r][tx] + s_h1[r + 1][tx] + s_h1[r + 2][tx];
            s_mid[r][tx] = (rok && mok0) ? sig1(s) : 0.0f;
        }
        if (tx < 2) {
            float s = s_h1[r][tx + 32] + s_h1[r + 1][tx + 32] + s_h1[r + 2][tx + 32];
            s_mid[r][tx + 32] = (rok && mok1) ? sig1(s) : 0.0f;
        }
    }
    __syncthreads();

    // ---- horizontal 3-sum of mid: 34 rows x 32 cols ----
    #pragma unroll
    for (int r = ty; r < 34; r += BYD) {
        s_h2[r][tx] = s_mid[r][tx] + s_mid[r][tx + 1] + s_mid[r][tx + 2];
    }
    __syncthreads();

    // ---- second conv (vertical 3-sum) + sigmoid -> 32x32 output ----
    #pragma unroll
    for (int r = ty; r < TS; r += BYD) {
        float s = s_h2[r][tx] + s_h2[r + 1][tx] + s_h2[r + 2][tx];
        oimg[(size_t)(by + r) * IMG + (bx + tx)] = sig2(s);
    }
}

extern "C" void kernel_launch(void* const* d_in, const int* in_sizes, int n_in,
                              void* d_out, int out_size) {
    const float* in = (const float*)d_in[0];
    float* out = (float*)d_out;
    dim3 grid(IMG / TS, IMG / TS, 32);   // (16,16,32)
    dim3 block(TS, BYD);                 // 256 threads
    blobber_fused_kernel<<<grid, block>>>(in, out);
}

// round 4
// speedup vs baseline: 1.7757x; 1.7757x over previous
#include <cuda_runtime.h>

// Blobber fused single pass (reference's 4 iterations are identical: each
// re-convolves `inputs`). out = sig2(box3(sig1(box3(in)))).
// Warp-streaming: each warp owns a 28-col strip + 2-col halo per side, walks
// 64 rows. Horizontal 3-sums via shuffles, vertical via register windows.
// No shared memory, no barriers.

#define IMG    512
#define STRIP  28
#define NSTRIP 19          // 19*28 = 532 >= 512
#define SEGROWS 64
#define NWARPS  8          // 8 warps * 64 rows = 512 rows per (strip,batch)

#define LOG2E 1.4426950408889634f
#define SCL   (1000.0f / 9.0f * LOG2E)
#define C1    (10.0f  * LOG2E)     // bias 0.01 * 1000 * log2e
#define C2    (900.0f * LOG2E)     // bias 0.9  * 1000 * log2e

// sigma((s/9 - b)*1000) = 1 / (1 + exp2(b*1000*log2e - s*(1000/9)*log2e))
__device__ __forceinline__ float sigx(float s, float cconst) {
    float e = exp2f(fmaf(s, -SCL, cconst));
    return __fdividef(1.0f, 1.0f + e);
}

__device__ __forceinline__ float ldrow(const float* __restrict__ img, int g,
                                       int c, bool colok) {
    float v = 0.0f;
    if (colok && (unsigned)g < (unsigned)IMG)
        v = __ldg(img + (g << 9) + c);
    return v;
}

struct Pipe {
    float h1a, h1b, h2a, h2b;
};

__device__ __forceinline__ void step(int g, float v, int s, int e, Pipe& p,
                                     bool colok, bool coutok,
                                     float* __restrict__ oimg, int c) {
    // horizontal 3-sum of input row g (valid lanes 1..30)
    float vl = __shfl_up_sync(0xffffffffu, v, 1);
    float vr = __shfl_down_sync(0xffffffffu, v, 1);
    float h1 = vl + v + vr;
    // mid row m = g-1: vertical 3-sum of h1, then sigmoid; exact 0 outside
    // the image (the second conv zero-pads the sigmoid map).
    float s1 = p.h1a + p.h1b + h1;
    p.h1a = p.h1b; p.h1b = h1;
    int m = g - 1;
    float mid = (colok && (unsigned)m < (unsigned)IMG) ? sigx(s1, C1) : 0.0f;
    // horizontal 3-sum of mid (valid lanes 2..29)
    float ml = __shfl_up_sync(0xffffffffu, mid, 1);
    float mr = __shfl_down_sync(0xffffffffu, mid, 1);
    float h2 = ml + mid + mr;
    // out row o = g-2: vertical 3-sum of h2, sigmoid, store
    float s2 = p.h2a + p.h2b + h2;
    p.h2a = p.h2b; p.h2b = h2;
    int o = g - 2;
    if (o >= s && coutok)
        oimg[(o << 9) + c] = sigx(s2, C2);
}

__global__ __launch_bounds__(32 * NWARPS)
void blobber_warpstream(const float* __restrict__ in, float* __restrict__ out) {
    const int lane = threadIdx.x & 31;
    const int wid  = threadIdx.x >> 5;

    const int  c0     = blockIdx.x * STRIP;
    const int  c      = c0 + lane - 2;                 // this lane's column
    const bool colok  = (unsigned)c < (unsigned)IMG;
    const bool coutok = (lane >= 2) && (lane <= 29) && (c < IMG);

    const float* img  = in  + (size_t)blockIdx.y * IMG * IMG;
    float*       oimg = out + (size_t)blockIdx.y * IMG * IMG;

    const int s = wid * SEGROWS;       // output rows [s, e)
    const int e = s + SEGROWS;

    Pipe p; p.h1a = 0.0f; p.h1b = 0.0f; p.h2a = 0.0f; p.h2b = 0.0f;

    // preload rows s-2 .. s+1
    float vb0 = ldrow(img, s - 2, c, colok);
    float vb1 = ldrow(img, s - 1, c, colok);
    float vb2 = ldrow(img, s + 0, c, colok);
    float vb3 = ldrow(img, s + 1, c, colok);

    // 68 pipeline steps (rows s-2 .. e+1), 17 batches of 4, prefetch 1 batch ahead
    #pragma unroll 1
    for (int gb = s - 2; gb < e + 2; gb += 4) {
        float vn0 = 0.f, vn1 = 0.f, vn2 = 0.f, vn3 = 0.f;
        if (gb + 4 < e + 2) {
            vn0 = ldrow(img, gb + 4, c, colok);
            vn1 = ldrow(img, gb + 5, c, colok);
            vn2 = ldrow(img, gb + 6, c, colok);
            vn3 = ldrow(img, gb + 7, c, colok);
        }
        step(gb + 0, vb0, s, e, p, colok, coutok, oimg, c);
        step(gb + 1, vb1, s, e, p, colok, coutok, oimg, c);
        step(gb + 2, vb2, s, e, p, colok, coutok, oimg, c);
        step(gb + 3, vb3, s, e, p, colok, coutok, oimg, c);
        vb0 = vn0; vb1 = vn1; vb2 = vn2; vb3 = vn3;
    }
}

extern "C" void kernel_launch(void* const* d_in, const int* in_sizes, int n_in,
                              void* d_out, int out_size) {
    const float* in = (const float*)d_in[0];
    float* out = (float*)d_out;
    dim3 grid(NSTRIP, 32);          // 19 strips x 32 batch images
    blobber_warpstream<<<grid, 32 * NWARPS>>>(in, out);
}

// round 5
// speedup vs baseline: 2.0688x; 1.1651x over previous
#include <cuda_runtime.h>

// Blobber fused single pass (reference's 4 iterations are identical — each
// re-convolves `inputs`). out = sig2(box3(sig1(box3(in)))).
// Warp-streaming, float2 per lane (64 cols/warp, 60 useful), PTX approx
// sigmoid (2 MUFU), 16-row segments for occupancy. No smem, no barriers.

#define IMG     512
#define OUTC    60
#define NSTRIP  9            // 9*60 = 540 >= 512
#define SEGROWS 16
#define NWARPS  8            // CTA covers 8*16 = 128 rows

#define LOG2E 1.4426950408889634f
#define SCL   (1000.0f / 9.0f * LOG2E)
#define C1    (10.0f  * LOG2E)      // bias 0.01*1000*log2e
#define C2    (900.0f * LOG2E)      // bias 0.9 *1000*log2e

// sigma((s/9 - b)*1000) = 1 / (1 + 2^(b*1000*log2e - s*(1000/9)*log2e))
__device__ __forceinline__ float sig_fast(float s, float cc) {
    float t = fmaf(s, -SCL, cc);
    float e;
    asm("ex2.approx.f32 %0, %1;" : "=f"(e) : "f"(t));
    float r;
    asm("rcp.approx.f32 %0, %1;" : "=f"(r) : "f"(e + 1.0f));
    return r;
}

__device__ __forceinline__ float2 ldrow2(const float* __restrict__ img,
                                         int col0, int g, bool colv) {
    float2 v = make_float2(0.0f, 0.0f);
    if (colv && (unsigned)g < (unsigned)IMG)
        v = *(const float2*)(img + (size_t)g * IMG + col0);
    return v;
}

struct Roll { float h1ax, h1ay, h1bx, h1by, h2ax, h2ay, h2bx, h2by; };

__device__ __forceinline__ void step(int g, float2 v, int S, Roll& R,
                                     bool colv, bool outok,
                                     float* __restrict__ oimg, int col0) {
    // horizontal 3-sums of input row g for this lane's 2 columns
    float vup = __shfl_up_sync(0xffffffffu, v.y, 1);    // col c-1
    float vdn = __shfl_down_sync(0xffffffffu, v.x, 1);  // col c+2
    float t   = v.x + v.y;
    float h1x = vup + t;
    float h1y = t + vdn;
    // mid row m = g-1: vertical sum + sigmoid; exact 0 outside image
    float s1x = R.h1ax + R.h1bx + h1x;
    float s1y = R.h1ay + R.h1by + h1y;
    R.h1ax = R.h1bx; R.h1bx = h1x;
    R.h1ay = R.h1by; R.h1by = h1y;
    float midx = 0.0f, midy = 0.0f;
    int m = g - 1;
    if ((unsigned)m < (unsigned)IMG && colv) {
        midx = sig_fast(s1x, C1);
        midy = sig_fast(s1y, C1);
    }
    // horizontal 3-sums of mid
    float mup = __shfl_up_sync(0xffffffffu, midy, 1);
    float mdn = __shfl_down_sync(0xffffffffu, midx, 1);
    float tm  = midx + midy;
    float h2x = mup + tm;
    float h2y = tm + mdn;
    // output row o = g-2
    float s2x = R.h2ax + R.h2bx + h2x;
    float s2y = R.h2ay + R.h2by + h2y;
    R.h2ax = R.h2bx; R.h2bx = h2x;
    R.h2ay = R.h2by; R.h2by = h2y;
    int o = g - 2;
    if (o >= S) {                       // warp-uniform: skips startup MUFUs
        if (outok) {
            float2 r = make_float2(sig_fast(s2x, C2), sig_fast(s2y, C2));
            *(float2*)(oimg + (size_t)o * IMG + col0) = r;
        }
    }
}

__global__ __launch_bounds__(32 * NWARPS)
void blobber_ws2(const float* __restrict__ in, float* __restrict__ out) {
    const int lane = threadIdx.x & 31;
    const int wid  = threadIdx.x >> 5;

    const int  col0  = blockIdx.x * OUTC - 2 + 2 * lane;   // even, [-2, 538]
    const bool colv  = (unsigned)col0 < (unsigned)IMG;     // float2 fully valid
    const bool outok = (lane >= 1) && (lane <= 30) && colv;

    const float* img  = in  + (size_t)blockIdx.z * IMG * IMG;
    float*       oimg = out + (size_t)blockIdx.z * IMG * IMG;

    const int S = (blockIdx.y * NWARPS + wid) * SEGROWS;   // output rows [S, S+16)

    Roll R;
    R.h1ax = R.h1ay = R.h1bx = R.h1by = 0.0f;
    R.h2ax = R.h2ay = R.h2bx = R.h2by = 0.0f;

    float2 vb0 = ldrow2(img, col0, S - 2, colv);
    float2 vb1 = ldrow2(img, col0, S - 1, colv);
    float2 vb2 = ldrow2(img, col0, S + 0, colv);
    float2 vb3 = ldrow2(img, col0, S + 1, colv);

    // 20 pipeline steps (rows S-2 .. S+17), 5 batches of 4, prefetch 1 ahead
    #pragma unroll 1
    for (int gb = S - 2; gb < S + 18; gb += 4) {
        float2 vn0 = make_float2(0.f, 0.f), vn1 = vn0, vn2 = vn0, vn3 = vn0;
        if (gb + 4 < S + 18) {
            vn0 = ldrow2(img, col0, gb + 4, colv);
            vn1 = ldrow2(img, col0, gb + 5, colv);
            vn2 = ldrow2(img, col0, gb + 6, colv);
            vn3 = ldrow2(img, col0, gb + 7, colv);
        }
        step(gb + 0, vb0, S, R, colv, outok, oimg, col0);
        step(gb + 1, vb1, S, R, colv, outok, oimg, col0);
        step(gb + 2, vb2, S, R, colv, outok, oimg, col0);
        step(gb + 3, vb3, S, R, colv, outok, oimg, col0);
        vb0 = vn0; vb1 = vn1; vb2 = vn2; vb3 = vn3;
    }
}

extern "C" void kernel_launch(void* const* d_in, const int* in_sizes, int n_in,
                              void* d_out, int out_size) {
    const float* in = (const float*)d_in[0];
    float* out = (float*)d_out;
    dim3 grid(NSTRIP, IMG / (SEGROWS * NWARPS), 32);   // (9, 4, 32) = 1152 CTAs
    blobber_ws2<<<grid, 32 * NWARPS>>>(in, out);
}

// round 7
// speedup vs baseline: 2.1213x; 1.0254x over previous
#include <cuda_runtime.h>

// Blobber fused single pass (reference's 4 iterations are identical — each
// re-convolves `inputs`). out = sig2(box3(sig1(box3(in)))).
// Warp-streaming, float2/lane (64 cols, 60 useful), 32-row segments.
// Interior segments: branch-free fully-specialized pipeline (no row checks).
// Boundary segments (2/16): guarded loop.

#define IMG     512
#define OUTC    60
#define NSTRIP  9            // 9*60 = 540 >= 512
#define SEG     32
#define NWARPS  8

#define LOG2E 1.4426950408889634f
#define SCL   (1000.0f / 9.0f * LOG2E)
#define C1    (10.0f  * LOG2E)
#define C2    (900.0f * LOG2E)

__device__ __forceinline__ float sig_fast(float s, float cc) {
    float t = fmaf(s, -SCL, cc);
    float e; asm("ex2.approx.f32 %0, %1;" : "=f"(e) : "f"(t));
    float r; asm("rcp.approx.f32 %0, %1;" : "=f"(r) : "f"(e + 1.0f));
    return r;
}

struct Roll { float h1ax, h1ay, h1bx, h1by, h2ax, h2ay, h2bx, h2by; };

// ---- interior step: rows statically valid, no checks ----
template<bool STORE>
__device__ __forceinline__ void stepF(float2 v, Roll& R, bool colv, bool outok,
                                      float*& op) {
    float vup = __shfl_up_sync(0xffffffffu, v.y, 1);
    float vdn = __shfl_down_sync(0xffffffffu, v.x, 1);
    float t   = v.x + v.y;
    float h1x = vup + t, h1y = t + vdn;
    float s1x = R.h1ax + R.h1bx + h1x;
    float s1y = R.h1ay + R.h1by + h1y;
    R.h1ax = R.h1bx; R.h1bx = h1x; R.h1ay = R.h1by; R.h1by = h1y;
    float midx = colv ? sig_fast(s1x, C1) : 0.0f;   // SEL, no branch
    float midy = colv ? sig_fast(s1y, C1) : 0.0f;
    float mup = __shfl_up_sync(0xffffffffu, midy, 1);
    float mdn = __shfl_down_sync(0xffffffffu, midx, 1);
    float tm  = midx + midy;
    float h2x = mup + tm, h2y = tm + mdn;
    float s2x = R.h2ax + R.h2bx + h2x;
    float s2y = R.h2ay + R.h2by + h2y;
    R.h2ax = R.h2bx; R.h2bx = h2x; R.h2ay = R.h2by; R.h2by = h2y;
    if (STORE) {
        if (outok)
            *(float2*)op = make_float2(sig_fast(s2x, C2), sig_fast(s2y, C2));
        op += IMG;
    }
}

// ---- guarded step for boundary segments ----
__device__ __forceinline__ void stepG(int g, float2 v, int S, Roll& R,
                                      bool colv, bool outok,
                                      float* __restrict__ oimg, int col0) {
    float vup = __shfl_up_sync(0xffffffffu, v.y, 1);
    float vdn = __shfl_down_sync(0xffffffffu, v.x, 1);
    float t   = v.x + v.y;
    float h1x = vup + t, h1y = t + vdn;
    float s1x = R.h1ax + R.h1bx + h1x;
    float s1y = R.h1ay + R.h1by + h1y;
    R.h1ax = R.h1bx; R.h1bx = h1x; R.h1ay = R.h1by; R.h1by = h1y;
    float midx = 0.0f, midy = 0.0f;
    int m = g - 1;                 // mid must be exact 0 outside the image
    if ((unsigned)m < (unsigned)IMG && colv) {
        midx = sig_fast(s1x, C1);
        midy = sig_fast(s1y, C1);
    }
    float mup = __shfl_up_sync(0xffffffffu, midy, 1);
    float mdn = __shfl_down_sync(0xffffffffu, midx, 1);
    float tm  = midx + midy;
    float h2x = mup + tm, h2y = tm + mdn;
    float s2x = R.h2ax + R.h2bx + h2x;
    float s2y = R.h2ay + R.h2by + h2y;
    R.h2ax = R.h2bx; R.h2bx = h2x; R.h2ay = R.h2by; R.h2by = h2y;
    int o = g - 2;
    if (o >= S && o < IMG && outok) {
        float2 r = make_float2(sig_fast(s2x, C2), sig_fast(s2y, C2));
        *(float2*)(oimg + (size_t)o * IMG + col0) = r;
    }
}

__device__ __forceinline__ float2 ld2p(const float* p, bool colv) {
    float2 v = make_float2(0.0f, 0.0f);
    if (colv) v = *(const float2*)p;
    return v;
}

__global__ __launch_bounds__(32 * NWARPS, 4)
void blobber_ws3(const float* __restrict__ in, float* __restrict__ out) {
    const int lane = threadIdx.x & 31;
    const int wid  = threadIdx.x >> 5;

    const int  col0  = blockIdx.x * OUTC - 2 + 2 * lane;   // even
    const bool colv  = (unsigned)col0 < (unsigned)IMG;     // whole float2 valid
    const bool outok = (lane >= 1) && (lane <= 30) && colv;

    const float* img  = in  + (size_t)blockIdx.z * IMG * IMG;
    float*       oimg = out + (size_t)blockIdx.z * IMG * IMG;

    const int S = (blockIdx.y * NWARPS + wid) * SEG;       // output rows [S, S+32)

    Roll R;
    R.h1ax = R.h1ay = R.h1bx = R.h1by = 0.0f;
    R.h2ax = R.h2ay = R.h2bx = R.h2by = 0.0f;

    if (S >= 2 && S + 33 < IMG) {
        // ---------- interior fast path ----------
        const float* ip = img + (size_t)(S - 2) * IMG + col0;
        float*       op = oimg + (size_t)S * IMG + col0;

        float2 b0 = ld2p(ip + 0 * IMG, colv);
        float2 b1 = ld2p(ip + 1 * IMG, colv);
        float2 b2 = ld2p(ip + 2 * IMG, colv);
        float2 b3 = ld2p(ip + 3 * IMG, colv);
        ip += 4 * IMG;

        // warm-up: 4 steps (no store), prefetch next batch
        float2 n0 = ld2p(ip + 0 * IMG, colv);
        float2 n1 = ld2p(ip + 1 * IMG, colv);
        float2 n2 = ld2p(ip + 2 * IMG, colv);
        float2 n3 = ld2p(ip + 3 * IMG, colv);
        ip += 4 * IMG;
        stepF<false>(b0, R, colv, outok, op);
        stepF<false>(b1, R, colv, outok, op);
        stepF<false>(b2, R, colv, outok, op);
        stepF<false>(b3, R, colv, outok, op);
        b0 = n0; b1 = n1; b2 = n2; b3 = n3;

        // 7 main batches with prefetch
        #pragma unroll 1
        for (int k = 0; k < 7; k++) {
            n0 = ld2p(ip + 0 * IMG, colv);
            n1 = ld2p(ip + 1 * IMG, colv);
            n2 = ld2p(ip + 2 * IMG, colv);
            n3 = ld2p(ip + 3 * IMG, colv);
            ip += 4 * IMG;
            stepF<true>(b0, R, colv, outok, op);
            stepF<true>(b1, R, colv, outok, op);
            stepF<true>(b2, R, colv, outok, op);
            stepF<true>(b3, R, colv, outok, op);
            b0 = n0; b1 = n1; b2 = n2; b3 = n3;
        }
        // drain batch (no prefetch)
        stepF<true>(b0, R, colv, outok, op);
        stepF<true>(b1, R, colv, outok, op);
        stepF<true>(b2, R, colv, outok, op);
        stepF<true>(b3, R, colv, outok, op);
    } else {
        // ---------- boundary path (S == 0 or S == 480) ----------
        float2 vb0, vb1, vb2, vb3;
        #define LDG_ROW(g) ((colv && (unsigned)(g) < (unsigned)IMG) \
            ? *(const float2*)(img + (size_t)(g) * IMG + col0) : make_float2(0.f, 0.f))
        vb0 = LDG_ROW(S - 2); vb1 = LDG_ROW(S - 1);
        vb2 = LDG_ROW(S + 0); vb3 = LDG_ROW(S + 1);
        #pragma unroll 1
        for (int gb = S - 2; gb < S + SEG + 2; gb += 4) {
            float2 n0 = make_float2(0.f, 0.f), n1 = n0, n2 = n0, n3 = n0;
            if (gb + 4 < S + SEG + 2) {
                n0 = LDG_ROW(gb + 4); n1 = LDG_ROW(gb + 5);
                n2 = LDG_ROW(gb + 6); n3 = LDG_ROW(gb + 7);
            }
            stepG(gb + 0, vb0, S, R, colv, outok, oimg, col0);
            stepG(gb + 1, vb1, S, R, colv, outok, oimg, col0);
            stepG(gb + 2, vb2, S, R, colv, outok, oimg, col0);
            stepG(gb + 3, vb3, S, R, colv, outok, oimg, col0);
            vb0 = n0; vb1 = n1; vb2 = n2; vb3 = n3;
        }
        #undef LDG_ROW
    }
}

extern "C" void kernel_launch(void* const* d_in, const int* in_sizes, int n_in,
                              void* d_out, int out_size) {
    const float* in = (const float*)d_in[0];
    float* out = (float*)d_out;
    dim3 grid(NSTRIP, IMG / (SEG * NWARPS), 32);   // (9, 2, 32) = 576 CTAs
    blobber_ws3<<<grid, 32 * NWARPS>>>(in, out);
}

// round 9
// speedup vs baseline: 2.8485x; 1.3428x over previous
#include <cuda_runtime.h>

// Blobber fused single pass (reference's 4 iterations are identical — each
// re-convolves `inputs`). out = sig2(box3(sig1(box3(in)))).
// Warp-streaming, float2/lane (64 cols, 60 useful), 32-row segments,
// tanh.approx sigmoid (1 MUFU), 3-tier specialization:
//   - interior rows + interior cols: zero predication
//   - interior rows + edge cols:     per-lane col selects only
//   - boundary rows (2/16):          fully guarded
// No smem, no barriers.

#define IMG     512
#define OUTC    60
#define NSTRIP  9            // 9*60 = 540 >= 512
#define SEG     32
#define NWARPS  4            // 128-thread CTAs

// sigma((s/9 - b)*1000) = 0.5 + 0.5*tanh(s*(500/9) - 500b)
#define STCL (500.0f / 9.0f)
#define C1T  (-5.0f)         // b = 0.01
#define C2T  (-450.0f)       // b = 0.9

__device__ __forceinline__ float sigt(float s, float cc) {
    float t = fmaf(s, STCL, cc);
    float th; asm("tanh.approx.f32 %0, %1;" : "=f"(th) : "f"(t));
    return fmaf(th, 0.5f, 0.5f);
}

struct Roll { float h1ax, h1ay, h1bx, h1by, h2ax, h2ay, h2bx, h2by; };

template<bool STORE, bool CHECK>
__device__ __forceinline__ void stepF(float2 v, Roll& R, bool colv, bool outok,
                                      float* st) {
    float vup = __shfl_up_sync(0xffffffffu, v.y, 1);
    float vdn = __shfl_down_sync(0xffffffffu, v.x, 1);
    float t   = v.x + v.y;
    float h1x = vup + t, h1y = t + vdn;
    float s1x = R.h1ax + R.h1bx + h1x;
    float s1y = R.h1ay + R.h1by + h1y;
    R.h1ax = R.h1bx; R.h1bx = h1x; R.h1ay = R.h1by; R.h1by = h1y;
    float midx, midy;
    if (CHECK) {                      // mid must be exact 0 outside the image
        midx = colv ? sigt(s1x, C1T) : 0.0f;
        midy = colv ? sigt(s1y, C1T) : 0.0f;
    } else {
        midx = sigt(s1x, C1T);
        midy = sigt(s1y, C1T);
    }
    float mup = __shfl_up_sync(0xffffffffu, midy, 1);
    float mdn = __shfl_down_sync(0xffffffffu, midx, 1);
    float tm  = midx + midy;
    float h2x = mup + tm, h2y = tm + mdn;
    float s2x = R.h2ax + R.h2bx + h2x;
    float s2y = R.h2ay + R.h2by + h2y;
    R.h2ax = R.h2bx; R.h2bx = h2x; R.h2ay = R.h2by; R.h2by = h2y;
    if (STORE && outok)
        *(float2*)st = make_float2(sigt(s2x, C2T), sigt(s2y, C2T));
}

template<bool CHECK>
__device__ __forceinline__ float2 ld2(const float* p, bool colv) {
    if (CHECK) {
        float2 v = make_float2(0.0f, 0.0f);
        if (colv) v = *(const float2*)p;
        return v;
    }
    return *(const float2*)p;
}

// interior-row segment: rows S-2..S+33 statically in-image
template<bool CHECK>
__device__ __forceinline__ void fast_seg(const float* ip, float* op,
                                         bool colv, bool outok) {
    Roll R;
    R.h1ax = R.h1ay = R.h1bx = R.h1by = 0.0f;
    R.h2ax = R.h2ay = R.h2bx = R.h2by = 0.0f;

    float2 b0 = ld2<CHECK>(ip + 0 * IMG, colv);
    float2 b1 = ld2<CHECK>(ip + 1 * IMG, colv);
    float2 b2 = ld2<CHECK>(ip + 2 * IMG, colv);
    float2 b3 = ld2<CHECK>(ip + 3 * IMG, colv);
    ip += 4 * IMG;

    float2 n0 = ld2<CHECK>(ip + 0 * IMG, colv);
    float2 n1 = ld2<CHECK>(ip + 1 * IMG, colv);
    float2 n2 = ld2<CHECK>(ip + 2 * IMG, colv);
    float2 n3 = ld2<CHECK>(ip + 3 * IMG, colv);
    ip += 4 * IMG;
    stepF<false, CHECK>(b0, R, colv, outok, op);
    stepF<false, CHECK>(b1, R, colv, outok, op);
    stepF<false, CHECK>(b2, R, colv, outok, op);
    stepF<false, CHECK>(b3, R, colv, outok, op);
    b0 = n0; b1 = n1; b2 = n2; b3 = n3;

    #pragma unroll 1
    for (int k = 0; k < 7; k++) {
        n0 = ld2<CHECK>(ip + 0 * IMG, colv);
        n1 = ld2<CHECK>(ip + 1 * IMG, colv);
        n2 = ld2<CHECK>(ip + 2 * IMG, colv);
        n3 = ld2<CHECK>(ip + 3 * IMG, colv);
        ip += 4 * IMG;
        stepF<true, CHECK>(b0, R, colv, outok, op + 0 * IMG);
        stepF<true, CHECK>(b1, R, colv, outok, op + 1 * IMG);
        stepF<true, CHECK>(b2, R, colv, outok, op + 2 * IMG);
        stepF<true, CHECK>(b3, R, colv, outok, op + 3 * IMG);
        op += 4 * IMG;
        b0 = n0; b1 = n1; b2 = n2; b3 = n3;
    }
    stepF<true, CHECK>(b0, R, colv, outok, op + 0 * IMG);
    stepF<true, CHECK>(b1, R, colv, outok, op + 1 * IMG);
    stepF<true, CHECK>(b2, R, colv, outok, op + 2 * IMG);
    stepF<true, CHECK>(b3, R, colv, outok, op + 3 * IMG);
}

// boundary-row guarded step
__device__ __forceinline__ void stepG(int g, float2 v, int S, Roll& R,
                                      bool colv, bool outok,
                                      float* __restrict__ oimg, int col0) {
    float vup = __shfl_up_sync(0xffffffffu, v.y, 1);
    float vdn = __shfl_down_sync(0xffffffffu, v.x, 1);
    float t   = v.x + v.y;
    float h1x = vup + t, h1y = t + vdn;
    float s1x = R.h1ax + R.h1bx + h1x;
    float s1y = R.h1ay + R.h1by + h1y;
    R.h1ax = R.h1bx; R.h1bx = h1x; R.h1ay = R.h1by; R.h1by = h1y;
    float midx = 0.0f, midy = 0.0f;
    int m = g - 1;
    if ((unsigned)m < (unsigned)IMG && colv) {
        midx = sigt(s1x, C1T);
        midy = sigt(s1y, C1T);
    }
    float mup = __shfl_up_sync(0xffffffffu, midy, 1);
    float mdn = __shfl_down_sync(0xffffffffu, midx, 1);
    float tm  = midx + midy;
    float h2x = mup + tm, h2y = tm + mdn;
    float s2x = R.h2ax + R.h2bx + h2x;
    float s2y = R.h2ay + R.h2by + h2y;
    R.h2ax = R.h2bx; R.h2bx = h2x; R.h2ay = R.h2by; R.h2by = h2y;
    int o = g - 2;
    if (o >= S && o < IMG && outok) {
        float2 r = make_float2(sigt(s2x, C2T), sigt(s2y, C2T));
        *(float2*)(oimg + (size_t)o * IMG + col0) = r;
    }
}

__global__ __launch_bounds__(32 * NWARPS, 8)
void blobber_ws4(const float* __restrict__ in, float* __restrict__ out) {
    const int lane = threadIdx.x & 31;
    const int wid  = threadIdx.x >> 5;

    const int  col0  = blockIdx.x * OUTC - 2 + 2 * lane;   // even
    const bool colv  = (unsigned)col0 < (unsigned)IMG;
    const bool outok = ((unsigned)(lane - 1) < 30u) && ((unsigned)col0 < (unsigned)IMG);

    const float* img  = in  + (size_t)blockIdx.z * IMG * IMG;
    float*       oimg = out + (size_t)blockIdx.z * IMG * IMG;

    const int S = (blockIdx.y * NWARPS + wid) * SEG;       // output rows [S, S+32)

    const bool row_int = (S >= 2) && (S + 33 < IMG);
    if (row_int) {
        const float* ip = img + (size_t)(S - 2) * IMG + col0;
        float*       op = oimg + (size_t)S * IMG + col0;
        if (blockIdx.x > 0 && blockIdx.x < NSTRIP - 1)
            fast_seg<false>(ip, op, colv, outok);
        else
            fast_seg<true>(ip, op, colv, outok);
    } else {
        Roll R;
        R.h1ax = R.h1ay = R.h1bx = R.h1by = 0.0f;
        R.h2ax = R.h2ay = R.h2bx = R.h2by = 0.0f;
        #define LDG_ROW(g) ((colv && (unsigned)(g) < (unsigned)IMG) \
            ? *(const float2*)(img + (size_t)(g) * IMG + col0) : make_float2(0.f, 0.f))
        float2 vb0 = LDG_ROW(S - 2), vb1 = LDG_ROW(S - 1);
        float2 vb2 = LDG_ROW(S + 0), vb3 = LDG_ROW(S + 1);
        #pragma unroll 1
        for (int gb = S - 2; gb < S + SEG + 2; gb += 4) {
            float2 n0 = make_float2(0.f, 0.f), n1 = n0, n2 = n0, n3 = n0;
            if (gb + 4 < S + SEG + 2) {
                n0 = LDG_ROW(gb + 4); n1 = LDG_ROW(gb + 5);
                n2 = LDG_ROW(gb + 6); n3 = LDG_ROW(gb + 7);
            }
            stepG(gb + 0, vb0, S, R, colv, outok, oimg, col0);
            stepG(gb + 1, vb1, S, R, colv, outok, oimg, col0);
            stepG(gb + 2, vb2, S, R, colv, outok, oimg, col0);
            stepG(gb + 3, vb3, S, R, colv, outok, oimg, col0);
            vb0 = n0; vb1 = n1; vb2 = n2; vb3 = n3;
        }
        #undef LDG_ROW
    }
}

extern "C" void kernel_launch(void* const* d_in, const int* in_sizes, int n_in,
                              void* d_out, int out_size) {
    const float* in = (const float*)d_in[0];
    float* out = (float*)d_out;
    dim3 grid(NSTRIP, IMG / (SEG * NWARPS), 32);   // (9, 4, 32) = 1152 CTAs
    blobber_ws4<<<grid, 32 * NWARPS>>>(in, out);
}